// round 1
// baseline (speedup 1.0000x reference)
#include <cuda_runtime.h>
#include <cstdint>

#define THRESH 0.5f
#define DECAY  0.2f

// ---------------- scratch (device globals; no allocation allowed) ------------
// spk1: [20][32][32][64][64] uint8
__device__ unsigned char g_spk1[20u * 32u * 32u * 64u * 64u];      // 167.8 MB
// c2:   [20][32][32][32][32] float
__device__ float         g_c2[20u * 32u * 32u * 32u * 32u];        //  83.9 MB
// spk2: [20][32][32][32][32] uint8
__device__ unsigned char g_spk2[20u * 32u * 32u * 32u * 32u];      //  21.0 MB
// c3:   [20][32][32][16][16] float
__device__ float         g_c3[20u * 32u * 32u * 16u * 16u];        //  21.0 MB

// =============================================================================
// Layer 1 fused: conv(2->32, 128->64, s2 p1) + membrane scan over all T.
// grid (16 tiles, 32 n), 256 threads, each thread owns one (y,x), all 32 co,
// loops T in 2 chunks of 10 (input is T-innermost so chunked loads are
// 40B-contiguous).
// =============================================================================
__global__ void __launch_bounds__(256, 2)
k1_fused(const float* __restrict__ in, const float* __restrict__ w1,
         const float* __restrict__ b1)
{
    const int n    = blockIdx.y;
    const int tile = blockIdx.x;
    const int ty0  = (tile >> 2) * 16;
    const int tx0  = (tile & 3) * 16;

    extern __shared__ float smem1[];
    float* in_s = smem1;                       // [2][33][33][10] = 21780 floats
    float* w_s  = smem1 + 2 * 33 * 33 * 10;    // [32][20] (18 used + pad)
    float* b_s  = w_s + 32 * 20;               // [32]

    const int tid = threadIdx.x;

    // stage weights/bias once
    for (int i = tid; i < 32 * 18; i += 256) {
        int co = i / 18, k = i % 18;
        w_s[co * 20 + k] = w1[i];
    }
    if (tid < 32) b_s[tid] = b1[tid];

    const int ly = tid >> 4, lx = tid & 15;
    const int gy = ty0 + ly, gx = tx0 + lx;

    float pot[32];
#pragma unroll
    for (int co = 0; co < 32; ++co) pot[co] = 0.f;
    unsigned int sp = 0u;  // spike bits from previous timestep

    const float* inb = in + (size_t)n * 2 * 128 * 128 * 20;

    for (int tc = 0; tc < 2; ++tc) {
        const int t0 = tc * 10;
        __syncthreads();
        // load input tile [2][33][33] x 10 timesteps
        for (int e = tid; e < 2 * 33 * 33; e += 256) {
            int ci = e / 1089;
            int r  = (e / 33) % 33;
            int c  = e % 33;
            int ih = 2 * ty0 - 1 + r;
            int iw = 2 * tx0 - 1 + c;
            float* dst = &in_s[e * 10];
            if (ih >= 0 && ih < 128 && iw >= 0 && iw < 128) {
                const float* src = inb + (((size_t)ci * 128 + ih) * 128 + iw) * 20 + t0;
#pragma unroll
                for (int k = 0; k < 5; ++k)
                    ((float2*)dst)[k] = ((const float2*)src)[k];
            } else {
#pragma unroll
                for (int k = 0; k < 10; ++k) dst[k] = 0.f;
            }
        }
        __syncthreads();

        for (int tt = 0; tt < 10; ++tt) {
            float v[18];
#pragma unroll
            for (int ci = 0; ci < 2; ++ci)
#pragma unroll
                for (int ky = 0; ky < 3; ++ky)
#pragma unroll
                    for (int kx = 0; kx < 3; ++kx)
                        v[ci * 9 + ky * 3 + kx] =
                            in_s[((ci * 33 + 2 * ly + ky) * 33 + 2 * lx + kx) * 10 + tt];

            const int t = t0 + tt;
            unsigned char* so =
                g_spk1 + ((size_t)t * 32 + n) * 32 * 4096 + gy * 64 + gx;
            unsigned int nsp = 0u;
#pragma unroll
            for (int co = 0; co < 32; ++co) {
                const float4* wr = (const float4*)&w_s[co * 20];
                float4 wa = wr[0], wb = wr[1], wc = wr[2], wd = wr[3];
                float  w16 = w_s[co * 20 + 16], w17 = w_s[co * 20 + 17];
                float acc = b_s[co];
                acc = fmaf(wa.x, v[0], acc);  acc = fmaf(wa.y, v[1], acc);
                acc = fmaf(wa.z, v[2], acc);  acc = fmaf(wa.w, v[3], acc);
                acc = fmaf(wb.x, v[4], acc);  acc = fmaf(wb.y, v[5], acc);
                acc = fmaf(wb.z, v[6], acc);  acc = fmaf(wb.w, v[7], acc);
                acc = fmaf(wc.x, v[8], acc);  acc = fmaf(wc.y, v[9], acc);
                acc = fmaf(wc.z, v[10], acc); acc = fmaf(wc.w, v[11], acc);
                acc = fmaf(wd.x, v[12], acc); acc = fmaf(wd.y, v[13], acc);
                acc = fmaf(wd.z, v[14], acc); acc = fmaf(wd.w, v[15], acc);
                acc = fmaf(w16,  v[16], acc); acc = fmaf(w17,  v[17], acc);

                float keep = ((sp >> co) & 1u) ? 0.f : pot[co] * DECAY;
                float u    = keep + acc;
                pot[co]    = u;
                unsigned int s = (u > THRESH) ? 1u : 0u;
                nsp |= (s << co);
                so[(size_t)co * 4096] = (unsigned char)s;
            }
            sp = nsp;
        }
    }
}

// =============================================================================
// Layer 2 conv (32->32, 64->32, s2 p1), parallel over t.
// grid (8 = 4 tiles x 2 co-halves, 32 n, 20 t), 256 threads (one (y,x) each,
// 16 co per thread).
// =============================================================================
__global__ void __launch_bounds__(256)
k2_conv(const float* __restrict__ w2, const float* __restrict__ b2)
{
    const int tile = blockIdx.x >> 1;
    const int coh  = blockIdx.x & 1;
    const int n    = blockIdx.y;
    const int t    = blockIdx.z;
    const int ty0  = (tile >> 1) * 16;
    const int tx0  = (tile & 1) * 16;
    const int cob  = coh * 16;

    extern __shared__ unsigned char smem2[];
    unsigned char* s_in = smem2;                         // [32][33][33] = 34848 B
    float* w_s = (float*)(smem2 + 34848);                // [ci=32][j=16][12]
    float* b_s = w_s + 32 * 16 * 12;                     // [16]

    const int tid = threadIdx.x;

    for (int i = tid; i < 16 * 32 * 9; i += 256) {
        int j = i / (32 * 9);
        int r = i % (32 * 9);
        int ci = r / 9, k = r % 9;
        w_s[(ci * 16 + j) * 12 + k] = w2[((size_t)(cob + j) * 32 + ci) * 9 + k];
    }
    if (tid < 16) b_s[tid] = b2[cob + tid];

    const unsigned char* sb = g_spk1 + ((size_t)t * 32 + n) * 32 * 4096;
    for (int e = tid; e < 32 * 33 * 33; e += 256) {
        int ci = e / 1089;
        int r  = (e / 33) % 33;
        int c  = e % 33;
        int ih = 2 * ty0 - 1 + r;
        int iw = 2 * tx0 - 1 + c;
        unsigned char val = 0;
        if (ih >= 0 && ih < 64 && iw >= 0 && iw < 64)
            val = sb[ci * 4096 + ih * 64 + iw];
        s_in[e] = val;
    }
    __syncthreads();

    const int ly = tid >> 4, lx = tid & 15;
    float acc[16];
#pragma unroll
    for (int j = 0; j < 16; ++j) acc[j] = b_s[j];

#pragma unroll 2
    for (int ci = 0; ci < 32; ++ci) {
        const int base = ci * 1089 + (2 * ly) * 33 + 2 * lx;
        float v0 = (float)s_in[base + 0];
        float v1 = (float)s_in[base + 1];
        float v2 = (float)s_in[base + 2];
        float v3 = (float)s_in[base + 33];
        float v4 = (float)s_in[base + 34];
        float v5 = (float)s_in[base + 35];
        float v6 = (float)s_in[base + 66];
        float v7 = (float)s_in[base + 67];
        float v8 = (float)s_in[base + 68];
#pragma unroll
        for (int j = 0; j < 16; ++j) {
            const float4* wr = (const float4*)&w_s[(ci * 16 + j) * 12];
            float4 wa = wr[0], wb = wr[1];
            float  w8 = w_s[(ci * 16 + j) * 12 + 8];
            float a = acc[j];
            a = fmaf(wa.x, v0, a); a = fmaf(wa.y, v1, a); a = fmaf(wa.z, v2, a);
            a = fmaf(wa.w, v3, a); a = fmaf(wb.x, v4, a); a = fmaf(wb.y, v5, a);
            a = fmaf(wb.z, v6, a); a = fmaf(wb.w, v7, a); a = fmaf(w8,  v8, a);
            acc[j] = a;
        }
    }

    float* outb = g_c2 + (((size_t)t * 32 + n) * 32 + cob) * 1024
                + (ty0 + ly) * 32 + (tx0 + lx);
#pragma unroll
    for (int j = 0; j < 16; ++j) outb[(size_t)j * 1024] = acc[j];
}

// =============================================================================
// Layer 2 membrane scan: elementwise over (n,co,y,x), sequential over T.
// =============================================================================
__global__ void k2_scan()
{
    const int e = blockIdx.x * 256 + threadIdx.x;   // 0 .. 1048575
    float pot = 0.f, s = 0.f;
#pragma unroll
    for (int t = 0; t < 20; ++t) {
        float u = pot * DECAY * (1.0f - s) + g_c2[(size_t)t * 1048576 + e];
        s   = (u > THRESH) ? 1.f : 0.f;
        pot = u;
        g_spk2[(size_t)t * 1048576 + e] = (unsigned char)s;
    }
}

// =============================================================================
// Layer 3 conv (32->32, 32->16, s2 p1), parallel over t.
// grid (4 co-quarters, 32 n, 20 t), 256 threads = full 16x16, 8 co per thread.
// =============================================================================
__global__ void __launch_bounds__(256)
k3_conv(const float* __restrict__ w3, const float* __restrict__ b3)
{
    const int cog = blockIdx.x;       // 0..3 -> co base = cog*8
    const int n   = blockIdx.y;
    const int t   = blockIdx.z;
    const int cob = cog * 8;

    extern __shared__ unsigned char smem3[];
    unsigned char* s_in = smem3;                          // [32][33][33]
    float* w_s = (float*)(smem3 + 34848);                 // [ci=32][j=8][12]
    float* b_s = w_s + 32 * 8 * 12;                       // [8]

    const int tid = threadIdx.x;

    for (int i = tid; i < 8 * 32 * 9; i += 256) {
        int j = i / (32 * 9);
        int r = i % (32 * 9);
        int ci = r / 9, k = r % 9;
        w_s[(ci * 8 + j) * 12 + k] = w3[((size_t)(cob + j) * 32 + ci) * 9 + k];
    }
    if (tid < 8) b_s[tid] = b3[cob + tid];

    const unsigned char* sb = g_spk2 + ((size_t)t * 32 + n) * 32 * 1024;
    for (int e = tid; e < 32 * 33 * 33; e += 256) {
        int ci = e / 1089;
        int r  = (e / 33) % 33;
        int c  = e % 33;
        int ih = r - 1;
        int iw = c - 1;
        unsigned char val = 0;
        if (ih >= 0 && ih < 32 && iw >= 0 && iw < 32)
            val = sb[ci * 1024 + ih * 32 + iw];
        s_in[e] = val;
    }
    __syncthreads();

    const int ly = tid >> 4, lx = tid & 15;
    float acc[8];
#pragma unroll
    for (int j = 0; j < 8; ++j) acc[j] = b_s[j];

#pragma unroll 2
    for (int ci = 0; ci < 32; ++ci) {
        const int base = ci * 1089 + (2 * ly) * 33 + 2 * lx;
        float v0 = (float)s_in[base + 0];
        float v1 = (float)s_in[base + 1];
        float v2 = (float)s_in[base + 2];
        float v3 = (float)s_in[base + 33];
        float v4 = (float)s_in[base + 34];
        float v5 = (float)s_in[base + 35];
        float v6 = (float)s_in[base + 66];
        float v7 = (float)s_in[base + 67];
        float v8 = (float)s_in[base + 68];
#pragma unroll
        for (int j = 0; j < 8; ++j) {
            const float4* wr = (const float4*)&w_s[(ci * 8 + j) * 12];
            float4 wa = wr[0], wb = wr[1];
            float  w8 = w_s[(ci * 8 + j) * 12 + 8];
            float a = acc[j];
            a = fmaf(wa.x, v0, a); a = fmaf(wa.y, v1, a); a = fmaf(wa.z, v2, a);
            a = fmaf(wa.w, v3, a); a = fmaf(wb.x, v4, a); a = fmaf(wb.y, v5, a);
            a = fmaf(wb.z, v6, a); a = fmaf(wb.w, v7, a); a = fmaf(w8,  v8, a);
            acc[j] = a;
        }
    }

    float* outb = g_c3 + (((size_t)t * 32 + n) * 32 + cob) * 256 + ly * 16 + lx;
#pragma unroll
    for (int j = 0; j < 8; ++j) outb[(size_t)j * 256] = acc[j];
}

// =============================================================================
// Layer 3 membrane scan -> final output, [bs][8192][T] with T innermost.
// =============================================================================
__global__ void k3_scan(float* __restrict__ out)
{
    const int e = blockIdx.x * 256 + threadIdx.x;   // 0 .. 262143 = (n,co,y,x)
    float pot = 0.f, s = 0.f;
    float res[20];
#pragma unroll
    for (int t = 0; t < 20; ++t) {
        float u = pot * DECAY * (1.0f - s) + g_c3[(size_t)t * 262144 + e];
        s   = (u > THRESH) ? 1.f : 0.f;
        pot = u;
        res[t] = s;
    }
    float* ob = out + (size_t)e * 20;
#pragma unroll
    for (int t = 0; t < 20; t += 4)
        *(float4*)(ob + t) = make_float4(res[t], res[t + 1], res[t + 2], res[t + 3]);
}

// =============================================================================
extern "C" void kernel_launch(void* const* d_in, const int* in_sizes, int n_in,
                              void* d_out, int out_size)
{
    const float* in = (const float*)d_in[0];
    const float* w1 = (const float*)d_in[1];
    const float* b1 = (const float*)d_in[2];
    const float* w2 = (const float*)d_in[3];
    const float* b2 = (const float*)d_in[4];
    const float* w3 = (const float*)d_in[5];
    const float* b3 = (const float*)d_in[6];
    float* out = (float*)d_out;

    const int SMEM1 = (2 * 33 * 33 * 10 + 32 * 20 + 32) * 4;          // 89808
    const int SMEM2 = 34848 + (32 * 16 * 12 + 16) * 4;                // 59488
    const int SMEM3 = 34848 + (32 * 8 * 12 + 8) * 4;                  // 47168

    cudaFuncSetAttribute(k1_fused, cudaFuncAttributeMaxDynamicSharedMemorySize, SMEM1);
    cudaFuncSetAttribute(k2_conv,  cudaFuncAttributeMaxDynamicSharedMemorySize, SMEM2);
    cudaFuncSetAttribute(k3_conv,  cudaFuncAttributeMaxDynamicSharedMemorySize, SMEM3);

    k1_fused<<<dim3(16, 32), 256, SMEM1>>>(in, w1, b1);
    k2_conv <<<dim3(8, 32, 20), 256, SMEM2>>>(w2, b2);
    k2_scan <<<4096, 256>>>();
    k3_conv <<<dim3(4, 32, 20), 256, SMEM3>>>(w3, b3);
    k3_scan <<<1024, 256>>>(out);
}

// round 2
// speedup vs baseline: 1.2079x; 1.2079x over previous
#include <cuda_runtime.h>
#include <cstdint>

#define THRESH 0.5f
#define DECAY  0.2f
#define ONE2   0x3F8000003F800000ULL

typedef unsigned long long u64;
typedef unsigned int u32;

// ---------------- scratch (device globals; no allocation allowed) ------------
__device__ u32   g_spk1m[20u * 32u * 64u * 64u];          // 10.5 MB  [t][n][y][x] bit ci
__device__ float g_c2[20u * 32u * 1024u * 32u];           // 83.9 MB  [t][n][yx][co]
__device__ u32   g_spk2m[20u * 32u * 1024u];              //  2.6 MB  [t][n][yx] bit ci
__device__ float g_c3[20u * 32u * 256u * 32u];            // 21.0 MB  [t][n][yx][co]

// ---------------- f32x2 helpers ----------------------------------------------
__device__ __forceinline__ void fma2(u64& d, u64 a, u64 b) {
    asm("fma.rn.f32x2 %0, %1, %2, %0;" : "+l"(d) : "l"(a), "l"(b));
}
__device__ __forceinline__ u64 pk2(float lo, float hi) {
    u64 r; asm("mov.b64 %0, {%1,%2};" : "=l"(r) : "f"(lo), "f"(hi)); return r;
}
__device__ __forceinline__ float2 up2(u64 v) {
    float2 r; asm("mov.b64 {%0,%1}, %2;" : "=f"(r.x), "=f"(r.y) : "l"(v)); return r;
}

// =============================================================================
// Layer 1 fused: conv(2->32, 128->64, s2 p1) + membrane scan over all T.
// grid (16 tiles, 32 n), 256 threads; thread owns one (y,x), 32 co as 16 pairs.
// Stores spike bitmask (u32) per (t, pos).
// =============================================================================
__global__ void __launch_bounds__(256, 2)
k1_fused(const float* __restrict__ in, const float* __restrict__ w1,
         const float* __restrict__ b1)
{
    const int n    = blockIdx.y;
    const int tile = blockIdx.x;
    const int ty0  = (tile >> 2) * 16;
    const int tx0  = (tile & 3) * 16;

    extern __shared__ float smem1[];
    float* in_s = smem1;                              // [2][33][33][10] = 21780 f
    u64*   wp   = (u64*)(smem1 + 21780);              // [18][16] co-pairs (byte 87120, 16B-aligned)
    u64*   bp   = wp + 18 * 16;                       // [16]

    const int tid = threadIdx.x;

    for (int i = tid; i < 18 * 16; i += 256) {
        int k = i >> 4, p = i & 15;
        wp[k * 16 + p] = pk2(w1[(2 * p) * 18 + k], w1[(2 * p + 1) * 18 + k]);
    }
    if (tid < 16) bp[tid] = pk2(b1[2 * tid], b1[2 * tid + 1]);

    const int ly = tid >> 4, lx = tid & 15;
    const int gy = ty0 + ly, gx = tx0 + lx;

    float pot[32];
#pragma unroll
    for (int c = 0; c < 32; ++c) pot[c] = 0.f;
    u32 sp = 0u;

    const float* inb = in + (size_t)n * 2 * 128 * 128 * 20;

    for (int tc = 0; tc < 2; ++tc) {
        const int t0 = tc * 10;
        __syncthreads();
        for (int e = tid; e < 2 * 33 * 33; e += 256) {
            int ci = e / 1089;
            int r  = (e / 33) % 33;
            int c  = e % 33;
            int ih = 2 * ty0 - 1 + r;
            int iw = 2 * tx0 - 1 + c;
            float* dst = &in_s[e * 10];
            if (ih >= 0 && ih < 128 && iw >= 0 && iw < 128) {
                const float* src = inb + (((size_t)ci * 128 + ih) * 128 + iw) * 20 + t0;
#pragma unroll
                for (int k = 0; k < 5; ++k)
                    ((float2*)dst)[k] = ((const float2*)src)[k];
            } else {
#pragma unroll
                for (int k = 0; k < 10; ++k) dst[k] = 0.f;
            }
        }
        __syncthreads();

        for (int tt = 0; tt < 10; ++tt) {
            float v[18];
#pragma unroll
            for (int ci = 0; ci < 2; ++ci)
#pragma unroll
                for (int ky = 0; ky < 3; ++ky)
#pragma unroll
                    for (int kx = 0; kx < 3; ++kx)
                        v[ci * 9 + ky * 3 + kx] =
                            in_s[((ci * 33 + 2 * ly + ky) * 33 + 2 * lx + kx) * 10 + tt];

            u64 acc[16];
#pragma unroll
            for (int p = 0; p < 16; ++p) acc[p] = bp[p];

#pragma unroll
            for (int k = 0; k < 18; ++k) {
                u64 vd = pk2(v[k], v[k]);
                const ulonglong2* wr = (const ulonglong2*)&wp[k * 16];
#pragma unroll
                for (int j = 0; j < 8; ++j) {
                    ulonglong2 q = wr[j];
                    fma2(acc[2 * j],     q.x, vd);
                    fma2(acc[2 * j + 1], q.y, vd);
                }
            }

            u32 nsp = 0u;
#pragma unroll
            for (int p = 0; p < 16; ++p) {
                float2 a = up2(acc[p]);
                int c0 = 2 * p;
                float k0 = ((sp >> c0) & 1u) ? 0.f : pot[c0] * DECAY;
                float u0 = k0 + a.x;
                pot[c0] = u0;
                nsp |= (u0 > THRESH ? 1u : 0u) << c0;
                int c1 = c0 + 1;
                float k1v = ((sp >> c1) & 1u) ? 0.f : pot[c1] * DECAY;
                float u1 = k1v + a.y;
                pot[c1] = u1;
                nsp |= (u1 > THRESH ? 1u : 0u) << c1;
            }
            sp = nsp;
            const int t = t0 + tt;
            g_spk1m[((size_t)t * 32 + n) * 4096 + gy * 64 + gx] = nsp;
        }
    }
}

// =============================================================================
// Layer 2 conv (32->32, 64->32, s2 p1), parallel over t. Bitmask input.
// grid (8 = 4 tiles x 2 co-halves, 32 n, 20 t), 256 threads: one (y,x),
// 16 co as 8 f32x2 pairs. Output co-innermost.
// =============================================================================
__global__ void __launch_bounds__(256)
k2_conv(const float* __restrict__ w2, const float* __restrict__ b2)
{
    const int tile = blockIdx.x >> 1;
    const int coh  = blockIdx.x & 1;
    const int n    = blockIdx.y;
    const int t    = blockIdx.z;
    const int ty0  = (tile >> 1) * 16;
    const int tx0  = (tile & 1) * 16;
    const int cob  = coh * 16;

    __shared__ u32 s_m[33 * 33 + 7];
    __shared__ __align__(16) u64 wp[32 * 9 * 8];   // [ci][k][pair]
    __shared__ u64 bp[8];

    const int tid = threadIdx.x;

    for (int i = tid; i < 32 * 9 * 8; i += 256) {
        int ci = i / 72, r = i % 72, k = r >> 3, p = r & 7;
        wp[i] = pk2(w2[(size_t)(cob + 2 * p) * 288 + ci * 9 + k],
                    w2[(size_t)(cob + 2 * p + 1) * 288 + ci * 9 + k]);
    }
    if (tid < 8) bp[tid] = pk2(b2[cob + 2 * tid], b2[cob + 2 * tid + 1]);

    const u32* mb = g_spk1m + ((size_t)t * 32 + n) * 4096;
    for (int e = tid; e < 33 * 33; e += 256) {
        int r = e / 33, c = e % 33;
        int ih = 2 * ty0 - 1 + r, iw = 2 * tx0 - 1 + c;
        s_m[e] = (ih >= 0 && ih < 64 && iw >= 0 && iw < 64) ? mb[ih * 64 + iw] : 0u;
    }
    __syncthreads();

    const int ly = tid >> 4, lx = tid & 15;
    u32 mk[9];
#pragma unroll
    for (int ky = 0; ky < 3; ++ky)
#pragma unroll
        for (int kx = 0; kx < 3; ++kx)
            mk[ky * 3 + kx] = s_m[(2 * ly + ky) * 33 + 2 * lx + kx];

    u64 acc[8];
#pragma unroll
    for (int p = 0; p < 8; ++p) acc[p] = bp[p];

#pragma unroll 4
    for (int ci = 0; ci < 32; ++ci) {
#pragma unroll
        for (int k = 0; k < 9; ++k) {
            u64 vd = ((mk[k] >> ci) & 1u) ? ONE2 : 0ULL;
            const ulonglong2* wr = (const ulonglong2*)&wp[(ci * 9 + k) * 8];
#pragma unroll
            for (int j = 0; j < 4; ++j) {
                ulonglong2 q = wr[j];
                fma2(acc[2 * j],     q.x, vd);
                fma2(acc[2 * j + 1], q.y, vd);
            }
        }
    }

    ulonglong2* o2 = (ulonglong2*)(g_c2 +
        (((size_t)t * 32 + n) * 1024 + (ty0 + ly) * 32 + tx0 + lx) * 32 + cob);
#pragma unroll
    for (int j = 0; j < 4; ++j) {
        ulonglong2 q; q.x = acc[2 * j]; q.y = acc[2 * j + 1];
        o2[j] = q;
    }
}

// =============================================================================
// Layer 2 membrane scan: lane = co, ballot -> bitmask for layer 3.
// =============================================================================
__global__ void k2_scan()
{
    const int gid = blockIdx.x * 256 + threadIdx.x;    // 1,048,576 total
    const int co = gid & 31;
    const int yx = (gid >> 5) & 1023;
    const int n  = gid >> 15;
    float pot = 0.f;
    u32 sbit = 0u;
#pragma unroll
    for (int t = 0; t < 20; ++t) {
        float c = g_c2[(((size_t)t * 32 + n) * 1024 + yx) * 32 + co];
        float u = (sbit ? 0.f : pot * DECAY) + c;
        sbit = (u > THRESH) ? 1u : 0u;
        pot = u;
        u32 m = __ballot_sync(0xFFFFFFFFu, sbit);
        if (co == 0) g_spk2m[((size_t)t * 32 + n) * 1024 + yx] = m;
    }
}

// =============================================================================
// Layer 3 conv (32->32, 32->16, s2 p1), parallel over t. Bitmask input.
// grid (2 co-halves, 32 n, 20 t), 256 threads = full 16x16, 16 co (8 pairs).
// =============================================================================
__global__ void __launch_bounds__(256)
k3_conv(const float* __restrict__ w3, const float* __restrict__ b3)
{
    const int coh = blockIdx.x;
    const int n   = blockIdx.y;
    const int t   = blockIdx.z;
    const int cob = coh * 16;

    __shared__ u32 s_m[33 * 33 + 7];
    __shared__ __align__(16) u64 wp[32 * 9 * 8];
    __shared__ u64 bp[8];

    const int tid = threadIdx.x;

    for (int i = tid; i < 32 * 9 * 8; i += 256) {
        int ci = i / 72, r = i % 72, k = r >> 3, p = r & 7;
        wp[i] = pk2(w3[(size_t)(cob + 2 * p) * 288 + ci * 9 + k],
                    w3[(size_t)(cob + 2 * p + 1) * 288 + ci * 9 + k]);
    }
    if (tid < 8) bp[tid] = pk2(b3[cob + 2 * tid], b3[cob + 2 * tid + 1]);

    const u32* mb = g_spk2m + ((size_t)t * 32 + n) * 1024;
    for (int e = tid; e < 33 * 33; e += 256) {
        int r = e / 33, c = e % 33;
        int ih = r - 1, iw = c - 1;
        s_m[e] = (ih >= 0 && ih < 32 && iw >= 0 && iw < 32) ? mb[ih * 32 + iw] : 0u;
    }
    __syncthreads();

    const int ly = tid >> 4, lx = tid & 15;
    u32 mk[9];
#pragma unroll
    for (int ky = 0; ky < 3; ++ky)
#pragma unroll
        for (int kx = 0; kx < 3; ++kx)
            mk[ky * 3 + kx] = s_m[(2 * ly + ky) * 33 + 2 * lx + kx];

    u64 acc[8];
#pragma unroll
    for (int p = 0; p < 8; ++p) acc[p] = bp[p];

#pragma unroll 4
    for (int ci = 0; ci < 32; ++ci) {
#pragma unroll
        for (int k = 0; k < 9; ++k) {
            u64 vd = ((mk[k] >> ci) & 1u) ? ONE2 : 0ULL;
            const ulonglong2* wr = (const ulonglong2*)&wp[(ci * 9 + k) * 8];
#pragma unroll
            for (int j = 0; j < 4; ++j) {
                ulonglong2 q = wr[j];
                fma2(acc[2 * j],     q.x, vd);
                fma2(acc[2 * j + 1], q.y, vd);
            }
        }
    }

    ulonglong2* o2 = (ulonglong2*)(g_c3 +
        (((size_t)t * 32 + n) * 256 + ly * 16 + lx) * 32 + cob);
#pragma unroll
    for (int j = 0; j < 4; ++j) {
        ulonglong2 q; q.x = acc[2 * j]; q.y = acc[2 * j + 1];
        o2[j] = q;
    }
}

// =============================================================================
// Layer 3 membrane scan -> final output [bs][8192][T], T innermost.
// =============================================================================
__global__ void k3_scan(float* __restrict__ out)
{
    const int gid = blockIdx.x * 256 + threadIdx.x;   // 262,144 total
    const int co = gid & 31;
    const int yx = (gid >> 5) & 255;
    const int n  = gid >> 13;
    float pot = 0.f;
    u32 sbit = 0u;
    float res[20];
#pragma unroll
    for (int t = 0; t < 20; ++t) {
        float c = g_c3[(((size_t)t * 32 + n) * 256 + yx) * 32 + co];
        float u = (sbit ? 0.f : pot * DECAY) + c;
        sbit = (u > THRESH) ? 1u : 0u;
        pot = u;
        res[t] = sbit ? 1.f : 0.f;
    }
    float* ob = out + ((size_t)(n * 32 + co) * 256 + yx) * 20;
#pragma unroll
    for (int t = 0; t < 20; t += 4)
        *(float4*)(ob + t) = make_float4(res[t], res[t + 1], res[t + 2], res[t + 3]);
}

// =============================================================================
extern "C" void kernel_launch(void* const* d_in, const int* in_sizes, int n_in,
                              void* d_out, int out_size)
{
    const float* in = (const float*)d_in[0];
    const float* w1 = (const float*)d_in[1];
    const float* b1 = (const float*)d_in[2];
    const float* w2 = (const float*)d_in[3];
    const float* b2 = (const float*)d_in[4];
    const float* w3 = (const float*)d_in[5];
    const float* b3 = (const float*)d_in[6];
    float* out = (float*)d_out;

    const int SMEM1 = 21780 * 4 + (18 * 16 + 16) * 8;   // 89552 B

    cudaFuncSetAttribute(k1_fused, cudaFuncAttributeMaxDynamicSharedMemorySize, SMEM1);

    k1_fused<<<dim3(16, 32), 256, SMEM1>>>(in, w1, b1);
    k2_conv <<<dim3(8, 32, 20), 256>>>(w2, b2);
    k2_scan <<<4096, 256>>>();
    k3_conv <<<dim3(2, 32, 20), 256>>>(w3, b3);
    k3_scan <<<1024, 256>>>(out);
}

// round 4
// speedup vs baseline: 2.1013x; 1.7396x over previous
#include <cuda_runtime.h>
#include <cstdint>

#define THRESH 0.5f
#define DECAY  0.2f
#define ONE2   0x3F8000003F800000ULL

typedef unsigned long long u64;
typedef unsigned int u32;
typedef unsigned short u16;

// ---------------- scratch (device globals) -----------------------------------
__device__ u16   g_spk1h[2u * 20u * 32u * 4096u];   // [coh][t][n][yx] 10.5 MB
__device__ float g_c2[20u * 32u * 1024u * 32u];     // [t][n][yx][co]  83.9 MB
__device__ u32   g_spk2m[20u * 32u * 1024u];        // [t][n][yx]       2.6 MB
__device__ float g_c3[20u * 32u * 256u * 32u];      // [t][n][yx][co]  21.0 MB

// ---------------- f32x2 helpers ----------------------------------------------
__device__ __forceinline__ void fma2(u64& d, u64 a, u64 b) {
    asm("fma.rn.f32x2 %0, %1, %2, %0;" : "+l"(d) : "l"(a), "l"(b));
}
__device__ __forceinline__ u64 pk2(float lo, float hi) {
    u64 r; asm("mov.b64 %0, {%1,%2};" : "=l"(r) : "f"(lo), "f"(hi)); return r;
}
__device__ __forceinline__ float2 up2(u64 v) {
    float2 r; asm("mov.b64 {%0,%1}, %2;" : "=f"(r.x), "=f"(r.y) : "l"(v)); return r;
}

// =============================================================================
// Layer 1 fused: conv(2->32, 128->64, s2 p1) + membrane scan over T.
// grid (16 tiles, 32 n), 256 thr = 2 co-halves x 16 y x 8 x-pairs.
// Thread: 2 x-adjacent positions, 16 co (8 f32x2 pairs). T chunked by 4.
// =============================================================================
__global__ void __launch_bounds__(256, 2)
k1_fused(const float* __restrict__ in, const float* __restrict__ w1,
         const float* __restrict__ b1)
{
    const int n    = blockIdx.y;
    const int tile = blockIdx.x;
    const int ty0  = (tile >> 2) * 16;
    const int tx0  = (tile & 3) * 16;

    __shared__ float in_s[4][2][33][33];   // [tt][ci][r][c]
    __shared__ u64   wp[18][16];           // [k][co-pair]
    __shared__ u64   bp[16];

    const int tid = threadIdx.x;
    const int coh = tid >> 7;
    const int ly  = (tid >> 3) & 15;
    const int lxq = tid & 7;

    // FIX (round-3 bug): 288 entries staged by 256 threads -> grid-stride loop.
    for (int i = tid; i < 18 * 16; i += 256) {
        int k = i >> 4, pr = i & 15;
        wp[k][pr] = pk2(w1[(2 * pr) * 18 + k], w1[(2 * pr + 1) * 18 + k]);
    }
    if (tid < 16) bp[tid] = pk2(b1[2 * tid], b1[2 * tid + 1]);

    float pot[2][16];
#pragma unroll
    for (int p = 0; p < 2; ++p)
#pragma unroll
        for (int c = 0; c < 16; ++c) pot[p][c] = 0.f;
    u32 sp[2] = {0u, 0u};

    const float* inb = in + (size_t)n * 2 * 128 * 128 * 20;
    const int gy = ty0 + ly;
    const int gx0 = tx0 + 2 * lxq;

    for (int tc = 0; tc < 5; ++tc) {
        const int t0 = tc * 4;
        __syncthreads();
        for (int e = tid; e < 2 * 33 * 33; e += 256) {
            int ci = e / 1089;
            int r  = (e / 33) % 33;
            int c  = e % 33;
            int ih = 2 * ty0 - 1 + r;
            int iw = 2 * tx0 - 1 + c;
            if (ih >= 0 && ih < 128 && iw >= 0 && iw < 128) {
                float4 v4 = *(const float4*)(inb + (((size_t)ci * 128 + ih) * 128 + iw) * 20 + t0);
                in_s[0][ci][r][c] = v4.x;
                in_s[1][ci][r][c] = v4.y;
                in_s[2][ci][r][c] = v4.z;
                in_s[3][ci][r][c] = v4.w;
            } else {
                in_s[0][ci][r][c] = 0.f;
                in_s[1][ci][r][c] = 0.f;
                in_s[2][ci][r][c] = 0.f;
                in_s[3][ci][r][c] = 0.f;
            }
        }
        __syncthreads();

        for (int tt = 0; tt < 4; ++tt) {
            const int t = t0 + tt;
            float v[2][3][5];
#pragma unroll
            for (int ci = 0; ci < 2; ++ci)
#pragma unroll
                for (int ky = 0; ky < 3; ++ky)
#pragma unroll
                    for (int c = 0; c < 5; ++c)
                        v[ci][ky][c] = in_s[tt][ci][2 * ly + ky][4 * lxq + c];

            u64 acc[2][8];
#pragma unroll
            for (int j = 0; j < 8; ++j) { acc[0][j] = bp[coh * 8 + j]; acc[1][j] = acc[0][j]; }

#pragma unroll
            for (int ci = 0; ci < 2; ++ci)
#pragma unroll
                for (int ky = 0; ky < 3; ++ky)
#pragma unroll
                    for (int kx = 0; kx < 3; ++kx) {
                        u64 vd0 = pk2(v[ci][ky][kx],     v[ci][ky][kx]);
                        u64 vd1 = pk2(v[ci][ky][kx + 2], v[ci][ky][kx + 2]);
                        const ulonglong2* wr =
                            (const ulonglong2*)&wp[ci * 9 + ky * 3 + kx][coh * 8];
#pragma unroll
                        for (int jj = 0; jj < 4; ++jj) {
                            ulonglong2 q = wr[jj];
                            fma2(acc[0][2 * jj],     q.x, vd0);
                            fma2(acc[1][2 * jj],     q.x, vd1);
                            fma2(acc[0][2 * jj + 1], q.y, vd0);
                            fma2(acc[1][2 * jj + 1], q.y, vd1);
                        }
                    }

#pragma unroll
            for (int p = 0; p < 2; ++p) {
                u32 nsp = 0u;
#pragma unroll
                for (int j = 0; j < 8; ++j) {
                    float2 a = up2(acc[p][j]);
                    int c0 = 2 * j;
                    float k0 = ((sp[p] >> c0) & 1u) ? 0.f : pot[p][c0] * DECAY;
                    float u0 = k0 + a.x;
                    pot[p][c0] = u0;
                    nsp |= (u0 > THRESH ? 1u : 0u) << c0;
                    int c1 = c0 + 1;
                    float k1v = ((sp[p] >> c1) & 1u) ? 0.f : pot[p][c1] * DECAY;
                    float u1 = k1v + a.y;
                    pot[p][c1] = u1;
                    nsp |= (u1 > THRESH ? 1u : 0u) << c1;
                }
                sp[p] = nsp;
                g_spk1h[(size_t)coh * 2621440u + ((size_t)t * 32 + n) * 4096
                        + gy * 64 + gx0 + p] = (u16)nsp;
            }
        }
    }
}

// =============================================================================
// Layer 2 conv (32->32, 64->32, s2 p1). Bitmask input, whole 32x32 image/block.
// grid (2 coh, 32 n, 20 t), 256 thr = 32 y x 8 x-quads; thread: 4 pos x 16 co.
// =============================================================================
__global__ void __launch_bounds__(256, 1)
k2_conv(const float* __restrict__ w2, const float* __restrict__ b2)
{
    const int coh = blockIdx.x;
    const int n   = blockIdx.y;
    const int t   = blockIdx.z;
    const int cob = coh * 16;

    __shared__ u32 s_m[65 * 65];
    __shared__ __align__(16) u64 wp[32 * 9 * 8];
    __shared__ u64 bp[8];

    const int tid = threadIdx.x;

    for (int i = tid; i < 32 * 9 * 8; i += 256) {
        int ci = i / 72, r = i % 72, k = r >> 3, pr = r & 7;
        wp[i] = pk2(w2[(size_t)(cob + 2 * pr) * 288 + ci * 9 + k],
                    w2[(size_t)(cob + 2 * pr + 1) * 288 + ci * 9 + k]);
    }
    if (tid < 8) bp[tid] = pk2(b2[cob + 2 * tid], b2[cob + 2 * tid + 1]);

    const u16* lo = g_spk1h + ((size_t)t * 32 + n) * 4096;
    const u16* hi = lo + 2621440u;
    for (int e = tid; e < 65 * 65; e += 256) {
        int r = e / 65, c = e % 65;
        int ih = r - 1, iw = c - 1;
        u32 m = 0u;
        if (ih >= 0 && ih < 64 && iw >= 0 && iw < 64)
            m = (u32)lo[ih * 64 + iw] | ((u32)hi[ih * 64 + iw] << 16);
        s_m[e] = m;
    }
    __syncthreads();

    const int ly = tid >> 3, xq = tid & 7;
    u32 mk[3][9];
#pragma unroll
    for (int ky = 0; ky < 3; ++ky)
#pragma unroll
        for (int c = 0; c < 9; ++c)
            mk[ky][c] = s_m[(2 * ly + ky) * 65 + 8 * xq + c];

    u64 acc[4][8];
#pragma unroll
    for (int p = 0; p < 4; ++p)
#pragma unroll
        for (int j = 0; j < 8; ++j) acc[p][j] = bp[j];

#pragma unroll 2
    for (int ci = 0; ci < 32; ++ci) {
#pragma unroll
        for (int ky = 0; ky < 3; ++ky) {
            u64 vd[9];
#pragma unroll
            for (int c = 0; c < 9; ++c)
                vd[c] = ((mk[ky][c] >> ci) & 1u) ? ONE2 : 0ULL;
#pragma unroll
            for (int kx = 0; kx < 3; ++kx) {
                const ulonglong2* wr = (const ulonglong2*)&wp[(ci * 9 + ky * 3 + kx) * 8];
#pragma unroll
                for (int jj = 0; jj < 4; ++jj) {
                    ulonglong2 q = wr[jj];
#pragma unroll
                    for (int p = 0; p < 4; ++p) {
                        fma2(acc[p][2 * jj],     q.x, vd[2 * p + kx]);
                        fma2(acc[p][2 * jj + 1], q.y, vd[2 * p + kx]);
                    }
                }
            }
        }
    }

    float* ob = g_c2 + (((size_t)t * 32 + n) * 1024 + ly * 32 + 4 * xq) * 32 + cob;
#pragma unroll
    for (int p = 0; p < 4; ++p) {
        ulonglong2* o2 = (ulonglong2*)(ob + p * 32);
#pragma unroll
        for (int jj = 0; jj < 4; ++jj) {
            ulonglong2 q; q.x = acc[p][2 * jj]; q.y = acc[p][2 * jj + 1];
            o2[jj] = q;
        }
    }
}

// =============================================================================
// Layer 2 membrane scan: lane = co, ballot -> bitmask for layer 3.
// =============================================================================
__global__ void k2_scan()
{
    const int gid = blockIdx.x * 256 + threadIdx.x;
    const int co = gid & 31;
    const int yx = (gid >> 5) & 1023;
    const int n  = gid >> 15;
    float pot = 0.f;
    u32 sbit = 0u;
#pragma unroll
    for (int t = 0; t < 20; ++t) {
        float c = g_c2[(((size_t)t * 32 + n) * 1024 + yx) * 32 + co];
        float u = (sbit ? 0.f : pot * DECAY) + c;
        sbit = (u > THRESH) ? 1u : 0u;
        pot = u;
        u32 m = __ballot_sync(0xFFFFFFFFu, sbit);
        if (co == 0) g_spk2m[((size_t)t * 32 + n) * 1024 + yx] = m;
    }
}

// =============================================================================
// Layer 3 conv (32->32, 32->16, s2 p1). Whole 16x16 image + all 32 co / block.
// grid (32 n, 20 t), 256 thr = 2 coh x 16 y x 8 x-pairs; thread: 2 pos x 16 co.
// =============================================================================
__global__ void __launch_bounds__(256, 2)
k3_conv(const float* __restrict__ w3, const float* __restrict__ b3)
{
    const int n = blockIdx.x;
    const int t = blockIdx.y;

    __shared__ u32 s_m[33 * 33];
    __shared__ __align__(16) u64 wp[2][32 * 9 * 8];
    __shared__ u64 bp[16];

    const int tid = threadIdx.x;

    for (int i = tid; i < 2 * 32 * 9 * 8; i += 256) {
        int half = i / 2304;
        int r2   = i % 2304;
        int ci = r2 / 72, r = r2 % 72, k = r >> 3, pr = r & 7;
        wp[half][r2] = pk2(w3[(size_t)(half * 16 + 2 * pr) * 288 + ci * 9 + k],
                           w3[(size_t)(half * 16 + 2 * pr + 1) * 288 + ci * 9 + k]);
    }
    if (tid < 16) bp[tid] = pk2(b3[2 * tid], b3[2 * tid + 1]);

    const u32* mb = g_spk2m + ((size_t)t * 32 + n) * 1024;
    for (int e = tid; e < 33 * 33; e += 256) {
        int r = e / 33, c = e % 33;
        int ih = r - 1, iw = c - 1;
        s_m[e] = (ih >= 0 && ih < 32 && iw >= 0 && iw < 32) ? mb[ih * 32 + iw] : 0u;
    }
    __syncthreads();

    const int coh = tid >> 7;
    const int ly  = (tid >> 3) & 15;
    const int xq  = tid & 7;

    u32 mk[3][5];
#pragma unroll
    for (int ky = 0; ky < 3; ++ky)
#pragma unroll
        for (int c = 0; c < 5; ++c)
            mk[ky][c] = s_m[(2 * ly + ky) * 33 + 4 * xq + c];

    u64 acc[2][8];
#pragma unroll
    for (int p = 0; p < 2; ++p)
#pragma unroll
        for (int j = 0; j < 8; ++j) acc[p][j] = bp[coh * 8 + j];

#pragma unroll 2
    for (int ci = 0; ci < 32; ++ci) {
#pragma unroll
        for (int ky = 0; ky < 3; ++ky) {
            u64 vd[5];
#pragma unroll
            for (int c = 0; c < 5; ++c)
                vd[c] = ((mk[ky][c] >> ci) & 1u) ? ONE2 : 0ULL;
#pragma unroll
            for (int kx = 0; kx < 3; ++kx) {
                const ulonglong2* wr =
                    (const ulonglong2*)&wp[coh][(ci * 9 + ky * 3 + kx) * 8];
#pragma unroll
                for (int jj = 0; jj < 4; ++jj) {
                    ulonglong2 q = wr[jj];
#pragma unroll
                    for (int p = 0; p < 2; ++p) {
                        fma2(acc[p][2 * jj],     q.x, vd[2 * p + kx]);
                        fma2(acc[p][2 * jj + 1], q.y, vd[2 * p + kx]);
                    }
                }
            }
        }
    }

    float* ob = g_c3 + (((size_t)t * 32 + n) * 256 + ly * 16 + 2 * xq) * 32 + coh * 16;
#pragma unroll
    for (int p = 0; p < 2; ++p) {
        ulonglong2* o2 = (ulonglong2*)(ob + p * 32);
#pragma unroll
        for (int jj = 0; jj < 4; ++jj) {
            ulonglong2 q; q.x = acc[p][2 * jj]; q.y = acc[p][2 * jj + 1];
            o2[jj] = q;
        }
    }
}

// =============================================================================
// Layer 3 membrane scan -> final output [bs][8192][T], T innermost.
// =============================================================================
__global__ void k3_scan(float* __restrict__ out)
{
    const int gid = blockIdx.x * 256 + threadIdx.x;
    const int co = gid & 31;
    const int yx = (gid >> 5) & 255;
    const int n  = gid >> 13;
    float pot = 0.f;
    u32 sbit = 0u;
    float res[20];
#pragma unroll
    for (int t = 0; t < 20; ++t) {
        float c = g_c3[(((size_t)t * 32 + n) * 256 + yx) * 32 + co];
        float u = (sbit ? 0.f : pot * DECAY) + c;
        sbit = (u > THRESH) ? 1u : 0u;
        pot = u;
        res[t] = sbit ? 1.f : 0.f;
    }
    float* ob = out + ((size_t)(n * 32 + co) * 256 + yx) * 20;
#pragma unroll
    for (int t = 0; t < 20; t += 4)
        *(float4*)(ob + t) = make_float4(res[t], res[t + 1], res[t + 2], res[t + 3]);
}

// =============================================================================
extern "C" void kernel_launch(void* const* d_in, const int* in_sizes, int n_in,
                              void* d_out, int out_size)
{
    const float* in = (const float*)d_in[0];
    const float* w1 = (const float*)d_in[1];
    const float* b1 = (const float*)d_in[2];
    const float* w2 = (const float*)d_in[3];
    const float* b2 = (const float*)d_in[4];
    const float* w3 = (const float*)d_in[5];
    const float* b3 = (const float*)d_in[6];
    float* out = (float*)d_out;

    k1_fused<<<dim3(16, 32), 256>>>(in, w1, b1);
    k2_conv <<<dim3(2, 32, 20), 256>>>(w2, b2);
    k2_scan <<<4096, 256>>>();
    k3_conv <<<dim3(32, 20), 256>>>(w3, b3);
    k3_scan <<<1024, 256>>>(out);
}

// round 5
// speedup vs baseline: 2.5684x; 1.2223x over previous
#include <cuda_runtime.h>
#include <cstdint>

#define THRESH 0.5f
#define DECAY  0.2f
#define ONE2   0x3F8000003F800000ULL

typedef unsigned long long u64;
typedef unsigned int u32;
typedef unsigned char u8;

// ---------------- scratch (device globals) -----------------------------------
__device__ u8    g_spk1b[20u * 32u * 4096u * 4u];   // [t][n][yx][coq] 10.5 MB
__device__ float g_c2[20u * 32u * 1024u * 32u];     // [t][n][yx][co]  83.9 MB
__device__ u32   g_spk2m[20u * 32u * 1024u];        // [t][n][yx]       2.6 MB
__device__ float g_c3[20u * 32u * 256u * 32u];      // [t][n][yx][co]  21.0 MB

// ---------------- f32x2 helpers ----------------------------------------------
__device__ __forceinline__ void fma2(u64& d, u64 a, u64 b) {
    asm("fma.rn.f32x2 %0, %1, %2, %0;" : "+l"(d) : "l"(a), "l"(b));
}
__device__ __forceinline__ u64 pk2(float lo, float hi) {
    u64 r; asm("mov.b64 %0, {%1,%2};" : "=l"(r) : "f"(lo), "f"(hi)); return r;
}
__device__ __forceinline__ float2 up2(u64 v) {
    float2 r; asm("mov.b64 {%0,%1}, %2;" : "=f"(r.x), "=f"(r.y) : "l"(v)); return r;
}

// =============================================================================
// Layer 1 fused: conv(2->32, 128->64, s2 p1) + membrane scan over T.
// grid (32 tiles, 32 n), 256 thr = 4 coq x 8 y x 8 xq (2 x-positions each).
// Thread: 2 positions x 8 co (4 pairs). T chunked by 4.
// =============================================================================
__global__ void __launch_bounds__(256, 3)
k1_fused(const float* __restrict__ in, const float* __restrict__ w1,
         const float* __restrict__ b1)
{
    const int n    = blockIdx.y;
    const int tile = blockIdx.x;
    const int ty0  = (tile >> 2) * 8;
    const int tx0  = (tile & 3) * 16;

    __shared__ float in_s[4][2][17][33];   // [tt][ci][r][c] = 17952 B
    __shared__ u64   wp[18][16];           // [tap][co-pair]
    __shared__ u64   bp[16];

    const int tid = threadIdx.x;
    const int coq = tid >> 6;              // 0..3
    const int ly  = (tid >> 3) & 7;
    const int lxq = tid & 7;

    for (int i = tid; i < 18 * 16; i += 256) {
        int k = i >> 4, pr = i & 15;
        wp[k][pr] = pk2(w1[(2 * pr) * 18 + k], w1[(2 * pr + 1) * 18 + k]);
    }
    if (tid < 16) bp[tid] = pk2(b1[2 * tid], b1[2 * tid + 1]);

    float pot[2][8];
#pragma unroll
    for (int p = 0; p < 2; ++p)
#pragma unroll
        for (int c = 0; c < 8; ++c) pot[p][c] = 0.f;
    u32 sp[2] = {0u, 0u};

    const float* inb = in + (size_t)n * 2 * 128 * 128 * 20;
    const int gy = ty0 + ly;
    const int gx0 = tx0 + 2 * lxq;

    for (int tc = 0; tc < 5; ++tc) {
        const int t0 = tc * 4;
        __syncthreads();
        for (int e = tid; e < 2 * 17 * 33; e += 256) {
            int ci = e / 561;
            int r  = (e / 33) % 17;
            int c  = e % 33;
            int ih = 2 * ty0 - 1 + r;
            int iw = 2 * tx0 - 1 + c;
            if (ih >= 0 && ih < 128 && iw >= 0 && iw < 128) {
                float4 v4 = *(const float4*)(inb + (((size_t)ci * 128 + ih) * 128 + iw) * 20 + t0);
                in_s[0][ci][r][c] = v4.x;
                in_s[1][ci][r][c] = v4.y;
                in_s[2][ci][r][c] = v4.z;
                in_s[3][ci][r][c] = v4.w;
            } else {
                in_s[0][ci][r][c] = 0.f;
                in_s[1][ci][r][c] = 0.f;
                in_s[2][ci][r][c] = 0.f;
                in_s[3][ci][r][c] = 0.f;
            }
        }
        __syncthreads();

        for (int tt = 0; tt < 4; ++tt) {
            const int t = t0 + tt;
            float v[2][3][5];
#pragma unroll
            for (int ci = 0; ci < 2; ++ci)
#pragma unroll
                for (int ky = 0; ky < 3; ++ky)
#pragma unroll
                    for (int c = 0; c < 5; ++c)
                        v[ci][ky][c] = in_s[tt][ci][2 * ly + ky][4 * lxq + c];

            u64 acc[2][4];
#pragma unroll
            for (int j = 0; j < 4; ++j) { acc[0][j] = bp[coq * 4 + j]; acc[1][j] = acc[0][j]; }

#pragma unroll
            for (int ci = 0; ci < 2; ++ci)
#pragma unroll
                for (int ky = 0; ky < 3; ++ky)
#pragma unroll
                    for (int kx = 0; kx < 3; ++kx) {
                        u64 vd0 = pk2(v[ci][ky][kx],     v[ci][ky][kx]);
                        u64 vd1 = pk2(v[ci][ky][kx + 2], v[ci][ky][kx + 2]);
                        const ulonglong2* wr =
                            (const ulonglong2*)&wp[ci * 9 + ky * 3 + kx][coq * 4];
                        ulonglong2 qa = wr[0], qb = wr[1];
                        fma2(acc[0][0], qa.x, vd0);
                        fma2(acc[1][0], qa.x, vd1);
                        fma2(acc[0][1], qa.y, vd0);
                        fma2(acc[1][1], qa.y, vd1);
                        fma2(acc[0][2], qb.x, vd0);
                        fma2(acc[1][2], qb.x, vd1);
                        fma2(acc[0][3], qb.y, vd0);
                        fma2(acc[1][3], qb.y, vd1);
                    }

#pragma unroll
            for (int p = 0; p < 2; ++p) {
                u32 nsp = 0u;
#pragma unroll
                for (int j = 0; j < 4; ++j) {
                    float2 a = up2(acc[p][j]);
                    int c0 = 2 * j;
                    float k0 = ((sp[p] >> c0) & 1u) ? 0.f : pot[p][c0] * DECAY;
                    float u0 = k0 + a.x;
                    pot[p][c0] = u0;
                    nsp |= (u0 > THRESH ? 1u : 0u) << c0;
                    int c1 = c0 + 1;
                    float k1v = ((sp[p] >> c1) & 1u) ? 0.f : pot[p][c1] * DECAY;
                    float u1 = k1v + a.y;
                    pot[p][c1] = u1;
                    nsp |= (u1 > THRESH ? 1u : 0u) << c1;
                }
                sp[p] = nsp;
                g_spk1b[(((size_t)t * 32 + n) * 4096 + gy * 64 + gx0 + p) * 4 + coq] = (u8)nsp;
            }
        }
    }
}

// =============================================================================
// Layer 2 conv (32->32, 64->32, s2 p1). Bitmask input, whole 32x32 image/block.
// grid (4 coq, 32 n, 20 t), 256 thr = 32 y x 8 xq; thread: 4 pos x 8 co.
// =============================================================================
__global__ void __launch_bounds__(256, 3)
k2_conv(const float* __restrict__ w2, const float* __restrict__ b2)
{
    const int q = blockIdx.x;
    const int n = blockIdx.y;
    const int t = blockIdx.z;
    const int cob = q * 8;

    __shared__ u32 s_m[65 * 65];
    __shared__ __align__(16) u64 wp[32 * 9 * 4];
    __shared__ u64 bp[4];

    const int tid = threadIdx.x;

    for (int i = tid; i < 32 * 9 * 4; i += 256) {
        int ci = i / 36, r = i % 36, k = r >> 2, pr = r & 3;
        wp[i] = pk2(w2[(size_t)(cob + 2 * pr) * 288 + ci * 9 + k],
                    w2[(size_t)(cob + 2 * pr + 1) * 288 + ci * 9 + k]);
    }
    if (tid < 4) bp[tid] = pk2(b2[cob + 2 * tid], b2[cob + 2 * tid + 1]);

    const u32* mb = (const u32*)g_spk1b + ((size_t)t * 32 + n) * 4096;
    for (int e = tid; e < 65 * 65; e += 256) {
        int r = e / 65, c = e % 65;
        int ih = r - 1, iw = c - 1;
        s_m[e] = (ih >= 0 && ih < 64 && iw >= 0 && iw < 64) ? mb[ih * 64 + iw] : 0u;
    }
    __syncthreads();

    const int ly = tid >> 3, xq = tid & 7;
    u32 mk[3][9];
#pragma unroll
    for (int ky = 0; ky < 3; ++ky)
#pragma unroll
        for (int c = 0; c < 9; ++c)
            mk[ky][c] = s_m[(2 * ly + ky) * 65 + 8 * xq + c];

    u64 acc[4][4];
#pragma unroll
    for (int p = 0; p < 4; ++p)
#pragma unroll
        for (int j = 0; j < 4; ++j) acc[p][j] = bp[j];

#pragma unroll 4
    for (int ci = 0; ci < 32; ++ci) {
#pragma unroll
        for (int ky = 0; ky < 3; ++ky) {
            u64 vd[9];
#pragma unroll
            for (int c = 0; c < 9; ++c)
                vd[c] = ((mk[ky][c] >> ci) & 1u) ? ONE2 : 0ULL;
#pragma unroll
            for (int kx = 0; kx < 3; ++kx) {
                const ulonglong2* wr = (const ulonglong2*)&wp[(ci * 9 + ky * 3 + kx) * 4];
                ulonglong2 qa = wr[0], qb = wr[1];
#pragma unroll
                for (int p = 0; p < 4; ++p) {
                    fma2(acc[p][0], qa.x, vd[2 * p + kx]);
                    fma2(acc[p][1], qa.y, vd[2 * p + kx]);
                    fma2(acc[p][2], qb.x, vd[2 * p + kx]);
                    fma2(acc[p][3], qb.y, vd[2 * p + kx]);
                }
            }
        }
    }

    float* ob = g_c2 + (((size_t)t * 32 + n) * 1024 + ly * 32 + 4 * xq) * 32 + cob;
#pragma unroll
    for (int p = 0; p < 4; ++p) {
        ulonglong2* o2 = (ulonglong2*)(ob + p * 32);
        ulonglong2 qa; qa.x = acc[p][0]; qa.y = acc[p][1];
        ulonglong2 qb; qb.x = acc[p][2]; qb.y = acc[p][3];
        o2[0] = qa; o2[1] = qb;
    }
}

// =============================================================================
// Layer 2 membrane scan: lane = co, ballot -> bitmask for layer 3.
// =============================================================================
__global__ void k2_scan()
{
    const int gid = blockIdx.x * 256 + threadIdx.x;
    const int co = gid & 31;
    const int yx = (gid >> 5) & 1023;
    const int n  = gid >> 15;
    float pot = 0.f;
    u32 sbit = 0u;
#pragma unroll
    for (int t = 0; t < 20; ++t) {
        float c = g_c2[(((size_t)t * 32 + n) * 1024 + yx) * 32 + co];
        float u = (sbit ? 0.f : pot * DECAY) + c;
        sbit = (u > THRESH) ? 1u : 0u;
        pot = u;
        u32 m = __ballot_sync(0xFFFFFFFFu, sbit);
        if (co == 0) g_spk2m[((size_t)t * 32 + n) * 1024 + yx] = m;
    }
}

// =============================================================================
// Layer 3 conv (32->32, 32->16, s2 p1). Whole 16x16 image + all co / block.
// grid (32 n, 20 t), 256 thr = 4 coq x 16 y x 4 xq; thread: 4 pos x 8 co.
// =============================================================================
__global__ void __launch_bounds__(256, 3)
k3_conv(const float* __restrict__ w3, const float* __restrict__ b3)
{
    const int n = blockIdx.x;
    const int t = blockIdx.y;

    __shared__ u32 s_m[33 * 33];
    __shared__ __align__(16) u64 wp[4][32 * 9 * 4];
    __shared__ u64 bp[16];

    const int tid = threadIdx.x;

    for (int i = tid; i < 4 * 32 * 9 * 4; i += 256) {
        int qg = i / 1152;
        int r2 = i % 1152;
        int ci = r2 / 36, r = r2 % 36, k = r >> 2, pr = r & 3;
        wp[qg][r2] = pk2(w3[(size_t)(qg * 8 + 2 * pr) * 288 + ci * 9 + k],
                         w3[(size_t)(qg * 8 + 2 * pr + 1) * 288 + ci * 9 + k]);
    }
    if (tid < 16) bp[tid] = pk2(b3[2 * tid], b3[2 * tid + 1]);

    const u32* mb = g_spk2m + ((size_t)t * 32 + n) * 1024;
    for (int e = tid; e < 33 * 33; e += 256) {
        int r = e / 33, c = e % 33;
        int ih = r - 1, iw = c - 1;
        s_m[e] = (ih >= 0 && ih < 32 && iw >= 0 && iw < 32) ? mb[ih * 32 + iw] : 0u;
    }
    __syncthreads();

    const int coq = tid >> 6;
    const int ly  = (tid >> 2) & 15;
    const int xq  = tid & 3;

    u32 mk[3][9];
#pragma unroll
    for (int ky = 0; ky < 3; ++ky)
#pragma unroll
        for (int c = 0; c < 9; ++c)
            mk[ky][c] = s_m[(2 * ly + ky) * 33 + 8 * xq + c];

    u64 acc[4][4];
#pragma unroll
    for (int p = 0; p < 4; ++p)
#pragma unroll
        for (int j = 0; j < 4; ++j) acc[p][j] = bp[coq * 4 + j];

#pragma unroll 4
    for (int ci = 0; ci < 32; ++ci) {
#pragma unroll
        for (int ky = 0; ky < 3; ++ky) {
            u64 vd[9];
#pragma unroll
            for (int c = 0; c < 9; ++c)
                vd[c] = ((mk[ky][c] >> ci) & 1u) ? ONE2 : 0ULL;
#pragma unroll
            for (int kx = 0; kx < 3; ++kx) {
                const ulonglong2* wr =
                    (const ulonglong2*)&wp[coq][(ci * 9 + ky * 3 + kx) * 4];
                ulonglong2 qa = wr[0], qb = wr[1];
#pragma unroll
                for (int p = 0; p < 4; ++p) {
                    fma2(acc[p][0], qa.x, vd[2 * p + kx]);
                    fma2(acc[p][1], qa.y, vd[2 * p + kx]);
                    fma2(acc[p][2], qb.x, vd[2 * p + kx]);
                    fma2(acc[p][3], qb.y, vd[2 * p + kx]);
                }
            }
        }
    }

    float* ob = g_c3 + (((size_t)t * 32 + n) * 256 + ly * 16 + 4 * xq) * 32 + coq * 8;
#pragma unroll
    for (int p = 0; p < 4; ++p) {
        ulonglong2* o2 = (ulonglong2*)(ob + p * 32);
        ulonglong2 qa; qa.x = acc[p][0]; qa.y = acc[p][1];
        ulonglong2 qb; qb.x = acc[p][2]; qb.y = acc[p][3];
        o2[0] = qa; o2[1] = qb;
    }
}

// =============================================================================
// Layer 3 membrane scan -> final output [bs][8192][T], T innermost.
// =============================================================================
__global__ void k3_scan(float* __restrict__ out)
{
    const int gid = blockIdx.x * 256 + threadIdx.x;
    const int co = gid & 31;
    const int yx = (gid >> 5) & 255;
    const int n  = gid >> 13;
    float pot = 0.f;
    u32 sbit = 0u;
    float res[20];
#pragma unroll
    for (int t = 0; t < 20; ++t) {
        float c = g_c3[(((size_t)t * 32 + n) * 256 + yx) * 32 + co];
        float u = (sbit ? 0.f : pot * DECAY) + c;
        sbit = (u > THRESH) ? 1u : 0u;
        pot = u;
        res[t] = sbit ? 1.f : 0.f;
    }
    float* ob = out + ((size_t)(n * 32 + co) * 256 + yx) * 20;
#pragma unroll
    for (int t = 0; t < 20; t += 4)
        *(float4*)(ob + t) = make_float4(res[t], res[t + 1], res[t + 2], res[t + 3]);
}

// =============================================================================
extern "C" void kernel_launch(void* const* d_in, const int* in_sizes, int n_in,
                              void* d_out, int out_size)
{
    const float* in = (const float*)d_in[0];
    const float* w1 = (const float*)d_in[1];
    const float* b1 = (const float*)d_in[2];
    const float* w2 = (const float*)d_in[3];
    const float* b2 = (const float*)d_in[4];
    const float* w3 = (const float*)d_in[5];
    const float* b3 = (const float*)d_in[6];
    float* out = (float*)d_out;

    k1_fused<<<dim3(32, 32), 256>>>(in, w1, b1);
    k2_conv <<<dim3(4, 32, 20), 256>>>(w2, b2);
    k2_scan <<<4096, 256>>>();
    k3_conv <<<dim3(32, 20), 256>>>(w3, b3);
    k3_scan <<<1024, 256>>>(out);
}